// round 2
// baseline (speedup 1.0000x reference)
#include <cuda_runtime.h>
#include <cstdint>

#define B_DIM 8
#define S_DIM 4096
#define H_DIM 512
#define M_TOT (B_DIM * S_DIM)   // 32768
#define N_TOT (2 * H_DIM)       // 1024
#define K_TOT H_DIM             // 512

// Scratch: softplus(GEMM) results, two contiguous planes (fully coalesced
// stores in GEMM epilogue and loads in the scan).
__device__ float g_Q[(size_t)M_TOT * H_DIM];  // 64 MB
__device__ float g_R[(size_t)M_TOT * H_DIM];  // 64 MB

// ---------------------------------------------------------------------------
// Phase 1: C = A * W^T + b, softplus, split into Q/R planes.
// TF32 mma.sync m16n8k8 (row.col): A row-major [M,K], W rows are K-contiguous
// which is exactly col-major K x N. Accuracy ~3e-4, well within 1e-3.
// ---------------------------------------------------------------------------

#define BM 128
#define BN 64
#define BK 32
#define NTHREADS 256
#define SKEW 4

__device__ __forceinline__ uint32_t f2tf32(float x) {
    uint32_t r;
    asm("cvt.rna.tf32.f32 %0, %1;" : "=r"(r) : "f"(x));
    return r;
}

__device__ __forceinline__ float softplus_f(float x) {
    // log(1+exp(x)) = max(x,0) + log1p(exp(-|x|))  (stable)
    return fmaxf(x, 0.0f) + log1pf(__expf(-fabsf(x)));
}

__device__ __forceinline__ void mma_tf32(float c[4], const uint32_t a[4], const uint32_t b[2]) {
    asm volatile(
        "mma.sync.aligned.m16n8k8.row.col.f32.tf32.tf32.f32 "
        "{%0,%1,%2,%3}, {%4,%5,%6,%7}, {%8,%9}, {%0,%1,%2,%3};"
        : "+f"(c[0]), "+f"(c[1]), "+f"(c[2]), "+f"(c[3])
        : "r"(a[0]), "r"(a[1]), "r"(a[2]), "r"(a[3]), "r"(b[0]), "r"(b[1]));
}

__global__ void __launch_bounds__(NTHREADS)
gemm_softplus_kernel(const float* __restrict__ A,
                     const float* __restrict__ W,
                     const float* __restrict__ bias) {
    __shared__ uint32_t As[BM][BK + SKEW];
    __shared__ uint32_t Bs[BN][BK + SKEW];

    const int bm = blockIdx.y * BM;
    const int bn = blockIdx.x * BN;
    const int tid = threadIdx.x;
    const int warp = tid >> 5;
    const int lane = tid & 31;
    const int wm = (warp >> 1) * 32;  // warp row offset within block: 0,32,64,96
    const int wn = (warp & 1) * 32;   // warp col offset within block: 0,32

    float acc[2][4][4];
#pragma unroll
    for (int i = 0; i < 2; i++)
#pragma unroll
        for (int j = 0; j < 4; j++)
#pragma unroll
            for (int c = 0; c < 4; c++) acc[i][j][c] = 0.0f;

    // staging registers for global->smem (hides LDG latency behind MMA)
    float4 a_stage[4];
    float4 b_stage[2];

    const int NKT = K_TOT / BK;  // 16

    // prologue: load k-tile 0
    {
        const int k0 = 0;
#pragma unroll
        for (int i = 0; i < 4; i++) {
            int idx = tid + i * NTHREADS;       // 0..1023
            int row = idx >> 3;                 // 0..127
            int c4  = idx & 7;
            a_stage[i] = *(const float4*)(A + (size_t)(bm + row) * K_TOT + k0 + c4 * 4);
        }
#pragma unroll
        for (int i = 0; i < 2; i++) {
            int idx = tid + i * NTHREADS;       // 0..511
            int row = idx >> 3;                 // 0..63
            int c4  = idx & 7;
            b_stage[i] = *(const float4*)(W + (size_t)(bn + row) * K_TOT + k0 + c4 * 4);
        }
    }

    for (int kt = 0; kt < NKT; kt++) {
        // commit staged regs to smem (converted to tf32 bits)
#pragma unroll
        for (int i = 0; i < 4; i++) {
            int idx = tid + i * NTHREADS;
            int row = idx >> 3;
            int c4  = idx & 7;
            uint4 p;
            p.x = f2tf32(a_stage[i].x);
            p.y = f2tf32(a_stage[i].y);
            p.z = f2tf32(a_stage[i].z);
            p.w = f2tf32(a_stage[i].w);
            *(uint4*)&As[row][c4 * 4] = p;
        }
#pragma unroll
        for (int i = 0; i < 2; i++) {
            int idx = tid + i * NTHREADS;
            int row = idx >> 3;
            int c4  = idx & 7;
            uint4 p;
            p.x = f2tf32(b_stage[i].x);
            p.y = f2tf32(b_stage[i].y);
            p.z = f2tf32(b_stage[i].z);
            p.w = f2tf32(b_stage[i].w);
            *(uint4*)&Bs[row][c4 * 4] = p;
        }
        __syncthreads();

        // prefetch next k-tile while computing
        if (kt + 1 < NKT) {
            const int k0 = (kt + 1) * BK;
#pragma unroll
            for (int i = 0; i < 4; i++) {
                int idx = tid + i * NTHREADS;
                int row = idx >> 3;
                int c4  = idx & 7;
                a_stage[i] = *(const float4*)(A + (size_t)(bm + row) * K_TOT + k0 + c4 * 4);
            }
#pragma unroll
            for (int i = 0; i < 2; i++) {
                int idx = tid + i * NTHREADS;
                int row = idx >> 3;
                int c4  = idx & 7;
                b_stage[i] = *(const float4*)(W + (size_t)(bn + row) * K_TOT + k0 + c4 * 4);
            }
        }

        // compute BK in 4 k8-slices
#pragma unroll
        for (int k8 = 0; k8 < 4; k8++) {
            const int c0 = k8 * 8 + (lane & 3);
            uint32_t afrag[2][4];
            uint32_t bfrag[4][2];
#pragma unroll
            for (int tm = 0; tm < 2; tm++) {
                int r0 = wm + tm * 16 + (lane >> 2);
                // PTX m16n8k8 tf32 A fragment:
                //   a0=(g,      tig), a1=(g+8,   tig),
                //   a2=(g,  tig+4),   a3=(g+8, tig+4)
                afrag[tm][0] = As[r0][c0];
                afrag[tm][1] = As[r0 + 8][c0];
                afrag[tm][2] = As[r0][c0 + 4];
                afrag[tm][3] = As[r0 + 8][c0 + 4];
            }
#pragma unroll
            for (int tn = 0; tn < 4; tn++) {
                int rb = wn + tn * 8 + (lane >> 2);
                bfrag[tn][0] = Bs[rb][c0];
                bfrag[tn][1] = Bs[rb][c0 + 4];
            }
#pragma unroll
            for (int tm = 0; tm < 2; tm++)
#pragma unroll
                for (int tn = 0; tn < 4; tn++)
                    mma_tf32(acc[tm][tn], afrag[tm], bfrag[tn]);
        }
        __syncthreads();
    }

    // Epilogue: add bias, softplus, write Q or R plane (contiguous per-plane).
    const bool is_q = (bn < H_DIM);
    float* plane = is_q ? g_Q : g_R;
    const int col_base_in_plane = is_q ? bn : (bn - H_DIM);

#pragma unroll
    for (int tm = 0; tm < 2; tm++) {
#pragma unroll
        for (int tn = 0; tn < 4; tn++) {
#pragma unroll
            for (int half = 0; half < 2; half++) {  // c pairs (0,1) and (2,3)
                int row = bm + wm + tm * 16 + (lane >> 2) + half * 8;
                int col = wn + tn * 8 + (lane & 3) * 2;  // within block tile
                int gcol = bn + col;                      // global output column
                float v0 = acc[tm][tn][half * 2 + 0] + __ldg(&bias[gcol]);
                float v1 = acc[tm][tn][half * 2 + 1] + __ldg(&bias[gcol + 1]);
                float2 sp;
                sp.x = softplus_f(v0);
                sp.y = softplus_f(v1);
                *(float2*)&plane[(size_t)row * H_DIM + col_base_in_plane + col] = sp;
            }
        }
    }
}

// ---------------------------------------------------------------------------
// Phase 2: sequential Kalman scan. One thread per (b,h) chain — 4096 threads.
// Latency-bound on the P -> rcp -> P carried chain (~36 cyc/step).
// ---------------------------------------------------------------------------
__global__ void __launch_bounds__(128)
scan_kernel(const float* __restrict__ lstm, float* __restrict__ out) {
    int idx = blockIdx.x * blockDim.x + threadIdx.x;  // 0..4095
    int b = idx >> 9;    // / 512
    int h = idx & 511;

    const float* zp = lstm + (size_t)b * S_DIM * H_DIM + h;
    const float* qp = g_Q + (size_t)b * S_DIM * H_DIM + h;
    const float* rp = g_R + (size_t)b * S_DIM * H_DIM + h;
    float* op = out + (size_t)b * S_DIM * H_DIM + h;

    float state = zp[0];
    float P = 0.1f;

#pragma unroll 4
    for (int s = 0; s < S_DIM; ++s) {
        float z = *zp;
        float q = *qp;
        float r = *rp;
        float P_pred = P + q;
        float denom = P_pred + r + 1e-6f;
        float K = __fdividef(P_pred, denom);
        state = state + K * (z - state);
        P = P_pred - K * P_pred;  // (1-K)*P_pred as single FFMA tail
        *op = state;
        zp += H_DIM;
        qp += H_DIM;
        rp += H_DIM;
        op += H_DIM;
    }
}

extern "C" void kernel_launch(void* const* d_in, const int* in_sizes, int n_in,
                              void* d_out, int out_size) {
    const float* lstm = (const float*)d_in[0];
    const float* W    = (const float*)d_in[1];
    const float* bias = (const float*)d_in[2];
    float* out = (float*)d_out;

    dim3 grid(N_TOT / BN, M_TOT / BM);  // (16, 256)
    gemm_softplus_kernel<<<grid, NTHREADS>>>(lstm, W, bias);

    scan_kernel<<<32, 128>>>(lstm, out);
}

// round 3
// speedup vs baseline: 1.5075x; 1.5075x over previous
#include <cuda_runtime.h>
#include <cstdint>

#define B_DIM 8
#define S_DIM 4096
#define H_DIM 512
#define M_TOT (B_DIM * S_DIM)   // 32768
#define N_TOT (2 * H_DIM)       // 1024
#define K_TOT H_DIM             // 512

__device__ float g_Q[(size_t)M_TOT * H_DIM];  // 64 MB
__device__ float g_R[(size_t)M_TOT * H_DIM];  // 64 MB

// ---------------------------------------------------------------------------
// Phase 1: C = A * W^T + b, softplus, split into Q/R planes.
// TF32 mma.sync m16n8k8 (row.col). fp32 bits fed directly (HW truncation to
// tf32): rel_err ~2-3e-4, well within 1e-3.
// ---------------------------------------------------------------------------

#define BM 128
#define BN 64
#define BK 32
#define NTHREADS 256
#define SKEW 4

__device__ __forceinline__ float softplus_f(float x) {
    return fmaxf(x, 0.0f) + log1pf(__expf(-fabsf(x)));
}

__device__ __forceinline__ void mma_tf32(float c[4], const uint32_t a[4], const uint32_t b[2]) {
    asm volatile(
        "mma.sync.aligned.m16n8k8.row.col.f32.tf32.tf32.f32 "
        "{%0,%1,%2,%3}, {%4,%5,%6,%7}, {%8,%9}, {%0,%1,%2,%3};"
        : "+f"(c[0]), "+f"(c[1]), "+f"(c[2]), "+f"(c[3])
        : "r"(a[0]), "r"(a[1]), "r"(a[2]), "r"(a[3]), "r"(b[0]), "r"(b[1]));
}

__global__ void __launch_bounds__(NTHREADS)
gemm_softplus_kernel(const float* __restrict__ A,
                     const float* __restrict__ W,
                     const float* __restrict__ bias) {
    __shared__ uint32_t As[BM][BK + SKEW];
    __shared__ uint32_t Bs[BN][BK + SKEW];

    const int bm = blockIdx.y * BM;
    const int bn = blockIdx.x * BN;
    const int tid = threadIdx.x;
    const int warp = tid >> 5;
    const int lane = tid & 31;
    const int wm = (warp >> 1) * 32;
    const int wn = (warp & 1) * 32;

    float acc[2][4][4];
#pragma unroll
    for (int i = 0; i < 2; i++)
#pragma unroll
        for (int j = 0; j < 4; j++)
#pragma unroll
            for (int c = 0; c < 4; c++) acc[i][j][c] = 0.0f;

    float4 a_stage[4];
    float4 b_stage[2];

    const int NKT = K_TOT / BK;  // 16

    {
        const int k0 = 0;
#pragma unroll
        for (int i = 0; i < 4; i++) {
            int idx = tid + i * NTHREADS;
            int row = idx >> 3;
            int c4  = idx & 7;
            a_stage[i] = *(const float4*)(A + (size_t)(bm + row) * K_TOT + k0 + c4 * 4);
        }
#pragma unroll
        for (int i = 0; i < 2; i++) {
            int idx = tid + i * NTHREADS;
            int row = idx >> 3;
            int c4  = idx & 7;
            b_stage[i] = *(const float4*)(W + (size_t)(bn + row) * K_TOT + k0 + c4 * 4);
        }
    }

    for (int kt = 0; kt < NKT; kt++) {
#pragma unroll
        for (int i = 0; i < 4; i++) {
            int idx = tid + i * NTHREADS;
            int row = idx >> 3;
            int c4  = idx & 7;
            uint4 p;
            p.x = __float_as_uint(a_stage[i].x);
            p.y = __float_as_uint(a_stage[i].y);
            p.z = __float_as_uint(a_stage[i].z);
            p.w = __float_as_uint(a_stage[i].w);
            *(uint4*)&As[row][c4 * 4] = p;
        }
#pragma unroll
        for (int i = 0; i < 2; i++) {
            int idx = tid + i * NTHREADS;
            int row = idx >> 3;
            int c4  = idx & 7;
            uint4 p;
            p.x = __float_as_uint(b_stage[i].x);
            p.y = __float_as_uint(b_stage[i].y);
            p.z = __float_as_uint(b_stage[i].z);
            p.w = __float_as_uint(b_stage[i].w);
            *(uint4*)&Bs[row][c4 * 4] = p;
        }
        __syncthreads();

        if (kt + 1 < NKT) {
            const int k0 = (kt + 1) * BK;
#pragma unroll
            for (int i = 0; i < 4; i++) {
                int idx = tid + i * NTHREADS;
                int row = idx >> 3;
                int c4  = idx & 7;
                a_stage[i] = *(const float4*)(A + (size_t)(bm + row) * K_TOT + k0 + c4 * 4);
            }
#pragma unroll
            for (int i = 0; i < 2; i++) {
                int idx = tid + i * NTHREADS;
                int row = idx >> 3;
                int c4  = idx & 7;
                b_stage[i] = *(const float4*)(W + (size_t)(bn + row) * K_TOT + k0 + c4 * 4);
            }
        }

#pragma unroll
        for (int k8 = 0; k8 < 4; k8++) {
            const int c0 = k8 * 8 + (lane & 3);
            uint32_t afrag[2][4];
            uint32_t bfrag[4][2];
#pragma unroll
            for (int tm = 0; tm < 2; tm++) {
                int r0 = wm + tm * 16 + (lane >> 2);
                afrag[tm][0] = As[r0][c0];
                afrag[tm][1] = As[r0 + 8][c0];
                afrag[tm][2] = As[r0][c0 + 4];
                afrag[tm][3] = As[r0 + 8][c0 + 4];
            }
#pragma unroll
            for (int tn = 0; tn < 4; tn++) {
                int rb = wn + tn * 8 + (lane >> 2);
                bfrag[tn][0] = Bs[rb][c0];
                bfrag[tn][1] = Bs[rb][c0 + 4];
            }
#pragma unroll
            for (int tm = 0; tm < 2; tm++)
#pragma unroll
                for (int tn = 0; tn < 4; tn++)
                    mma_tf32(acc[tm][tn], afrag[tm], bfrag[tn]);
        }
        __syncthreads();
    }

    const bool is_q = (bn < H_DIM);
    float* plane = is_q ? g_Q : g_R;
    const int col_base_in_plane = is_q ? bn : (bn - H_DIM);

#pragma unroll
    for (int tm = 0; tm < 2; tm++) {
#pragma unroll
        for (int tn = 0; tn < 4; tn++) {
#pragma unroll
            for (int half = 0; half < 2; half++) {
                int row = bm + wm + tm * 16 + (lane >> 2) + half * 8;
                int col = wn + tn * 8 + (lane & 3) * 2;
                int gcol = bn + col;
                float v0 = acc[tm][tn][half * 2 + 0] + __ldg(&bias[gcol]);
                float v1 = acc[tm][tn][half * 2 + 1] + __ldg(&bias[gcol + 1]);
                float2 sp;
                sp.x = softplus_f(v0);
                sp.y = softplus_f(v1);
                *(float2*)&plane[(size_t)row * H_DIM + col_base_in_plane + col] = sp;
            }
        }
    }
}

// ---------------------------------------------------------------------------
// Phase 2: sequential Kalman scan with software-pipelined register prefetch.
// Addresses are recurrence-independent, so loads for chunk c+1 are issued
// before computing chunk c: DRAM latency hidden behind the ~28 cyc/step
// arithmetic chain (add->add->rcp.approx->mul).
// ---------------------------------------------------------------------------
#define U 16
#define NCH (S_DIM / U)   // 256

__device__ __forceinline__ void load_chunk(float zb[U], float qb[U], float rb[U],
                                           const float* __restrict__ zp,
                                           const float* __restrict__ qp,
                                           const float* __restrict__ rp,
                                           int c) {
    const size_t base = (size_t)c * U * H_DIM;
#pragma unroll
    for (int i = 0; i < U; i++) {
        size_t off = base + (size_t)i * H_DIM;
        zb[i] = __ldg(zp + off);
        qb[i] = __ldg(qp + off);
        rb[i] = __ldg(rp + off);
    }
}

__device__ __forceinline__ void compute_chunk(const float zb[U], const float qb[U],
                                              const float rb[U],
                                              float& state, float& P,
                                              float* __restrict__ op, int c) {
    const size_t base = (size_t)c * U * H_DIM;
#pragma unroll
    for (int i = 0; i < U; i++) {
        float P_pred = P + qb[i];
        float rr = rb[i] + 1e-6f;
        float denom = P_pred + rr;
        float inv;
        asm("rcp.approx.f32 %0, %1;" : "=f"(inv) : "f"(denom));
        float K = P_pred * inv;
        state = state + K * (zb[i] - state);
        P = P_pred * rr * inv;   // == (1-K)*P_pred exactly in real arithmetic
        op[base + (size_t)i * H_DIM] = state;
    }
}

__global__ void __launch_bounds__(32)
scan_kernel(const float* __restrict__ lstm, float* __restrict__ out) {
    int idx = blockIdx.x * 32 + threadIdx.x;  // 0..4095
    int b = idx >> 9;
    int h = idx & 511;

    const float* zp = lstm + (size_t)b * S_DIM * H_DIM + h;
    const float* qp = g_Q + (size_t)b * S_DIM * H_DIM + h;
    const float* rp = g_R + (size_t)b * S_DIM * H_DIM + h;
    float* op = out + (size_t)b * S_DIM * H_DIM + h;

    float state = zp[0];
    float P = 0.1f;

    float z0[U], q0[U], r0[U];
    float z1[U], q1[U], r1[U];

    load_chunk(z0, q0, r0, zp, qp, rp, 0);

    for (int c = 0; c < NCH; c += 2) {
        load_chunk(z1, q1, r1, zp, qp, rp, c + 1);      // NCH even -> always valid
        compute_chunk(z0, q0, r0, state, P, op, c);
        if (c + 2 < NCH)
            load_chunk(z0, q0, r0, zp, qp, rp, c + 2);
        compute_chunk(z1, q1, r1, state, P, op, c + 1);
    }
}

extern "C" void kernel_launch(void* const* d_in, const int* in_sizes, int n_in,
                              void* d_out, int out_size) {
    const float* lstm = (const float*)d_in[0];
    const float* W    = (const float*)d_in[1];
    const float* bias = (const float*)d_in[2];
    float* out = (float*)d_out;

    dim3 grid(N_TOT / BN, M_TOT / BM);  // (16, 256)
    gemm_softplus_kernel<<<grid, NTHREADS>>>(lstm, W, bias);

    scan_kernel<<<128, 32>>>(lstm, out);
}

// round 4
// speedup vs baseline: 1.9701x; 1.3069x over previous
#include <cuda_runtime.h>
#include <cstdint>

#define B_DIM 8
#define S_DIM 4096
#define H_DIM 512
#define M_TOT (B_DIM * S_DIM)   // 32768
#define N_TOT (2 * H_DIM)       // 1024
#define K_TOT H_DIM             // 512

// Scratch planes, CHAIN-MAJOR layout: g_Q[chain][s], chain = b*512 + h.
// Scan reads become per-lane contiguous (vectorizable float4).
__device__ float g_Q[(size_t)M_TOT * H_DIM];  // 64 MB
__device__ float g_R[(size_t)M_TOT * H_DIM];  // 64 MB

// ---------------------------------------------------------------------------
// Phase 1: C = A * W^T + b, softplus, split into Q/R planes (transposed).
// TF32 mma.sync m16n8k8 (row.col). fp32 bits fed directly (HW truncation).
// ---------------------------------------------------------------------------

#define BM 128
#define BN 64
#define BK 32
#define NTHREADS 256
#define SKEW 4

__device__ __forceinline__ float softplus_f(float x) {
    return fmaxf(x, 0.0f) + log1pf(__expf(-fabsf(x)));
}

__device__ __forceinline__ void mma_tf32(float c[4], const uint32_t a[4], const uint32_t b[2]) {
    asm volatile(
        "mma.sync.aligned.m16n8k8.row.col.f32.tf32.tf32.f32 "
        "{%0,%1,%2,%3}, {%4,%5,%6,%7}, {%8,%9}, {%0,%1,%2,%3};"
        : "+f"(c[0]), "+f"(c[1]), "+f"(c[2]), "+f"(c[3])
        : "r"(a[0]), "r"(a[1]), "r"(a[2]), "r"(a[3]), "r"(b[0]), "r"(b[1]));
}

__global__ void __launch_bounds__(NTHREADS)
gemm_softplus_kernel(const float* __restrict__ A,
                     const float* __restrict__ W,
                     const float* __restrict__ bias) {
    __shared__ uint32_t As[BM][BK + SKEW];
    __shared__ uint32_t Bs[BN][BK + SKEW];

    const int bm = blockIdx.y * BM;
    const int bn = blockIdx.x * BN;
    const int tid = threadIdx.x;
    const int warp = tid >> 5;
    const int lane = tid & 31;
    const int wm = (warp >> 1) * 32;
    const int wn = (warp & 1) * 32;

    float acc[2][4][4];
#pragma unroll
    for (int i = 0; i < 2; i++)
#pragma unroll
        for (int j = 0; j < 4; j++)
#pragma unroll
            for (int c = 0; c < 4; c++) acc[i][j][c] = 0.0f;

    float4 a_stage[4];
    float4 b_stage[2];

    const int NKT = K_TOT / BK;  // 16

    {
        const int k0 = 0;
#pragma unroll
        for (int i = 0; i < 4; i++) {
            int idx = tid + i * NTHREADS;
            int row = idx >> 3;
            int c4  = idx & 7;
            a_stage[i] = *(const float4*)(A + (size_t)(bm + row) * K_TOT + k0 + c4 * 4);
        }
#pragma unroll
        for (int i = 0; i < 2; i++) {
            int idx = tid + i * NTHREADS;
            int row = idx >> 3;
            int c4  = idx & 7;
            b_stage[i] = *(const float4*)(W + (size_t)(bn + row) * K_TOT + k0 + c4 * 4);
        }
    }

    for (int kt = 0; kt < NKT; kt++) {
#pragma unroll
        for (int i = 0; i < 4; i++) {
            int idx = tid + i * NTHREADS;
            int row = idx >> 3;
            int c4  = idx & 7;
            uint4 p;
            p.x = __float_as_uint(a_stage[i].x);
            p.y = __float_as_uint(a_stage[i].y);
            p.z = __float_as_uint(a_stage[i].z);
            p.w = __float_as_uint(a_stage[i].w);
            *(uint4*)&As[row][c4 * 4] = p;
        }
#pragma unroll
        for (int i = 0; i < 2; i++) {
            int idx = tid + i * NTHREADS;
            int row = idx >> 3;
            int c4  = idx & 7;
            uint4 p;
            p.x = __float_as_uint(b_stage[i].x);
            p.y = __float_as_uint(b_stage[i].y);
            p.z = __float_as_uint(b_stage[i].z);
            p.w = __float_as_uint(b_stage[i].w);
            *(uint4*)&Bs[row][c4 * 4] = p;
        }
        __syncthreads();

        if (kt + 1 < NKT) {
            const int k0 = (kt + 1) * BK;
#pragma unroll
            for (int i = 0; i < 4; i++) {
                int idx = tid + i * NTHREADS;
                int row = idx >> 3;
                int c4  = idx & 7;
                a_stage[i] = *(const float4*)(A + (size_t)(bm + row) * K_TOT + k0 + c4 * 4);
            }
#pragma unroll
            for (int i = 0; i < 2; i++) {
                int idx = tid + i * NTHREADS;
                int row = idx >> 3;
                int c4  = idx & 7;
                b_stage[i] = *(const float4*)(W + (size_t)(bn + row) * K_TOT + k0 + c4 * 4);
            }
        }

#pragma unroll
        for (int k8 = 0; k8 < 4; k8++) {
            const int c0 = k8 * 8 + (lane & 3);
            uint32_t afrag[2][4];
            uint32_t bfrag[4][2];
#pragma unroll
            for (int tm = 0; tm < 2; tm++) {
                int r0 = wm + tm * 16 + (lane >> 2);
                afrag[tm][0] = As[r0][c0];
                afrag[tm][1] = As[r0 + 8][c0];
                afrag[tm][2] = As[r0][c0 + 4];
                afrag[tm][3] = As[r0 + 8][c0 + 4];
            }
#pragma unroll
            for (int tn = 0; tn < 4; tn++) {
                int rb = wn + tn * 8 + (lane >> 2);
                bfrag[tn][0] = Bs[rb][c0];
                bfrag[tn][1] = Bs[rb][c0 + 4];
            }
#pragma unroll
            for (int tm = 0; tm < 2; tm++)
#pragma unroll
                for (int tn = 0; tn < 4; tn++)
                    mma_tf32(acc[tm][tn], afrag[tm], bfrag[tn]);
        }
        __syncthreads();
    }

    // Epilogue: bias + softplus, TRANSPOSED store into chain-major planes.
    // plane[(b*512 + hcol) * S + s], where global row = b*4096 + s.
    const bool is_q = (bn < H_DIM);
    float* plane = is_q ? g_Q : g_R;
    const int col_plane_base = is_q ? bn : (bn - H_DIM);

#pragma unroll
    for (int tm = 0; tm < 2; tm++) {
#pragma unroll
        for (int tn = 0; tn < 4; tn++) {
#pragma unroll
            for (int half = 0; half < 2; half++) {
                int row = bm + wm + tm * 16 + (lane >> 2) + half * 8;  // b*4096 + s
                int b = row >> 12;
                int s = row & 4095;
                int col = wn + tn * 8 + (lane & 3) * 2;
                int gcol = bn + col;
                int hcol = col_plane_base + col;
                float v0 = acc[tm][tn][half * 2 + 0] + __ldg(&bias[gcol]);
                float v1 = acc[tm][tn][half * 2 + 1] + __ldg(&bias[gcol + 1]);
                plane[((size_t)(b * H_DIM + hcol)) * S_DIM + s]     = softplus_f(v0);
                plane[((size_t)(b * H_DIM + hcol + 1)) * S_DIM + s] = softplus_f(v1);
            }
        }
    }
}

// ---------------------------------------------------------------------------
// Phase 2: Kalman scan, register-pipelined with 4 rotating buffers
// (prefetch distance 3 chunks ~= 672 cyc > DRAM latency). q/r are read
// chain-major (contiguous, float4); z/out remain [b,s,h] (warp-coalesced).
// ---------------------------------------------------------------------------
#define U 8
#define NCH (S_DIM / U)   // 512
#define NBUF 4

struct Chunk {
    float4 q[2];
    float4 r[2];
    float  z[U];
};

__device__ __forceinline__ void load_chunk(Chunk& ch,
                                           const float* __restrict__ qc,
                                           const float* __restrict__ rc,
                                           const float* __restrict__ zp,
                                           int c) {
    const float4* q4 = (const float4*)(qc + (size_t)c * U);
    const float4* r4 = (const float4*)(rc + (size_t)c * U);
    ch.q[0] = __ldg(q4);
    ch.q[1] = __ldg(q4 + 1);
    ch.r[0] = __ldg(r4);
    ch.r[1] = __ldg(r4 + 1);
    const float* zc = zp + (size_t)c * U * H_DIM;
#pragma unroll
    for (int i = 0; i < U; i++)
        ch.z[i] = __ldg(zc + (size_t)i * H_DIM);
}

__device__ __forceinline__ float comp(const float4& v, int i) {
    return i == 0 ? v.x : (i == 1 ? v.y : (i == 2 ? v.z : v.w));
}

__device__ __forceinline__ void compute_chunk(const Chunk& ch,
                                              float& state, float& P,
                                              float* __restrict__ op, int c) {
    float* oc = op + (size_t)c * U * H_DIM;
#pragma unroll
    for (int i = 0; i < U; i++) {
        float q = comp(ch.q[i >> 2], i & 3);
        float r = comp(ch.r[i >> 2], i & 3);
        float P_pred = P + q;
        float rr = r + 1e-6f;
        float denom = P_pred + rr;
        float inv;
        asm("rcp.approx.f32 %0, %1;" : "=f"(inv) : "f"(denom));
        float K = P_pred * inv;
        state = fmaf(K, ch.z[i] - state, state);
        P = P_pred * rr * inv;   // == (1-K)*P_pred
        oc[(size_t)i * H_DIM] = state;
    }
}

__global__ void __launch_bounds__(32, 1)
scan_kernel(const float* __restrict__ lstm, float* __restrict__ out) {
    int idx = blockIdx.x * 32 + threadIdx.x;  // 0..4095 == chain id
    int b = idx >> 9;
    int h = idx & 511;

    const float* zp = lstm + (size_t)b * S_DIM * H_DIM + h;   // stride H per step
    const float* qc = g_Q + (size_t)idx * S_DIM;              // contiguous
    const float* rc = g_R + (size_t)idx * S_DIM;
    float* op = out + (size_t)b * S_DIM * H_DIM + h;

    float state = zp[0];
    float P = 0.1f;

    Chunk buf0, buf1, buf2, buf3;

    load_chunk(buf0, qc, rc, zp, 0);
    load_chunk(buf1, qc, rc, zp, 1);
    load_chunk(buf2, qc, rc, zp, 2);

    for (int c = 0; c < NCH; c += NBUF) {
        load_chunk(buf3, qc, rc, zp, c + 3);              // c+3 <= 511 always
        compute_chunk(buf0, state, P, op, c);
        if (c + 4 < NCH) load_chunk(buf0, qc, rc, zp, c + 4);
        compute_chunk(buf1, state, P, op, c + 1);
        if (c + 5 < NCH) load_chunk(buf1, qc, rc, zp, c + 5);
        compute_chunk(buf2, state, P, op, c + 2);
        if (c + 6 < NCH) load_chunk(buf2, qc, rc, zp, c + 6);
        compute_chunk(buf3, state, P, op, c + 3);
    }
}

extern "C" void kernel_launch(void* const* d_in, const int* in_sizes, int n_in,
                              void* d_out, int out_size) {
    const float* lstm = (const float*)d_in[0];
    const float* W    = (const float*)d_in[1];
    const float* bias = (const float*)d_in[2];
    float* out = (float*)d_out;

    dim3 grid(N_TOT / BN, M_TOT / BM);  // (16, 256)
    gemm_softplus_kernel<<<grid, NTHREADS>>>(lstm, W, bias);

    scan_kernel<<<128, 32>>>(lstm, out);
}